// round 5
// baseline (speedup 1.0000x reference)
#include <cuda_runtime.h>
#include <math.h>

#define EPS 1e-20f
#define KK 9

__device__ __forceinline__ float softplusf(float x) {
    return fmaxf(x, 0.0f) + log1pf(expf(-fabsf(x)));
}

// packed f32x2 FMA (sm_103a FFMA2 — only reachable via PTX)
#define FMA2(acc, a, b) \
    asm("fma.rn.f32x2 %0, %1, %2, %3;" : "=l"(acc) : "l"(a), "l"(b), "l"(acc))

// compute U,V for 4 consecutive x and store parity-split
__device__ __forceinline__ void stage_store(
    float2 (*Ue)[128], float2 (*Uo)[132], int r, int g4, float wp,
    float4 fs, float4 fcd, float4 fgx, float4 fcg)
{
    const float se[4]  = {fs.x,  fs.y,  fs.z,  fs.w};
    const float cde[4] = {fcd.x, fcd.y, fcd.z, fcd.w};
    const float ge[4]  = {fgx.x, fgx.y, fgx.z, fgx.w};
    const float cge[4] = {fcg.x, fcg.y, fcg.z, fcg.w};
    float u[4], v[4];
    #pragma unroll
    for (int e = 0; e < 4; e++) {
        const int x = g4 * 4 + e;
        const float cgds = (x == 0 || x == 255)
                         ? 0.0f
                         : se[e] * se[e] * se[e] * cde[e] * cde[e];
        u[e] = wp * cge[e] * ge[e];
        v[e] = wp * cge[e] + cgds;
    }
    float4 ev = make_float4(u[0], v[0], u[2], v[2]);
    *(float4*)&Ue[r][2 * g4] = ev;              // even x -> [x/2]
    Uo[r][2 * g4 + 1] = make_float2(u[1], v[1]); // odd x -> [x/2 + 1]
    Uo[r][2 * g4 + 2] = make_float2(u[3], v[3]);
}

// One fused kernel: stage1 + spatial + incremental channel mix.
// Stage1 exact simplification (reference's pad_r/pad_l are edge-zero masks):
//   cgx_from_ds = s^3*cd^2 for 0<x<W-1 else 0; gx_from_ds term contributes 0.
//   U = wp*cgx*gx ; V = wp*cgx + cgx_from_ds
// Per channel: P = (sum_k sw_k*sprod_k*U_k) * scale_c ; Q likewise with V,
//   scale_c = 1/((wp+1)(S+eps)).
// Channel mix accumulated incrementally: acc[o] += {cw[o,c],cw[o,c]} * {P,Q}.
__global__ __launch_bounds__(512, 1) void fused_kernel(
    const float* __restrict__ s_in, const float* __restrict__ cd,
    const float* __restrict__ gx,   const float* __restrict__ cgx,
    const float* __restrict__ sprod,
    const float* __restrict__ w_prop, const float* __restrict__ spatial_weight,
    const float* __restrict__ channel_weight, const float* __restrict__ bias,
    float* __restrict__ out)
{
    __shared__ float2 sUVe[2][9][128];
    __shared__ float2 sUVo[2][9][132];   // [..][..][0] = zero pad (x = -1)
    __shared__ unsigned long long scw2[32 * 32];  // [c][o], {w,w} packed
    __shared__ float s_sw[32 * KK];
    __shared__ float s_scale[32];
    __shared__ float s_wp[32];
    __shared__ float swsums[16];
    __shared__ float sbias[32];
    __shared__ float s_invS2_4;

    const int t   = threadIdx.x;
    const int b   = blockIdx.x >> 5;
    const int hg  = blockIdx.x & 31;
    const int ho0 = hg * 4;
    const int ir0 = 2 * ho0 - 1;

    // staging map: item = t -> r 0..7; threads t<64 also do r=8
    const int r_m  = t >> 6;
    const int g4_m = t & 63;
    const bool extra = (t < 64);

    // pixel map: 512 pixels = 4 rows x 128
    const int hloc = t >> 7;
    const int wo   = t & 127;
    const int ho   = ho0 + hloc;

    // ---------------- prologue: issue gmem loads for c = 0 ----------------
    float sp_cur[9];
    {
        const unsigned spb = (unsigned)(b * 32 + 0) * (KK * 16384u)
                           + (unsigned)ho * 128u + wo;
        #pragma unroll
        for (int k = 0; k < 9; k++)
            sp_cur[k] = __ldcs(&sprod[spb + (unsigned)k * 16384u]);
    }
    float4 L_s = {0,0,0,0}, L_cd = {0,0,0,0}, L_gx = {0,0,0,0}, L_cg = {0,0,0,0};
    float4 E_s = {0,0,0,0}, E_cd = {0,0,0,0}, E_gx = {0,0,0,0}, E_cg = {0,0,0,0};
    {
        const unsigned plane = (unsigned)(b * 32 + 0) * 65536u;
        const int ir = ir0 + r_m;
        if ((unsigned)ir < 256u) {
            const unsigned base = plane + (unsigned)ir * 256u + g4_m * 4u;
            L_s  = *(const float4*)(s_in + base);
            L_cd = *(const float4*)(cd   + base);
            L_gx = *(const float4*)(gx   + base);
            L_cg = *(const float4*)(cgx  + base);
        }
        const int ir2 = ir0 + 8;
        if (extra && (unsigned)ir2 < 256u) {
            const unsigned base = plane + (unsigned)ir2 * 256u + g4_m * 4u;
            E_s  = *(const float4*)(s_in + base);
            E_cd = *(const float4*)(cd   + base);
            E_gx = *(const float4*)(gx   + base);
            E_cg = *(const float4*)(cgx  + base);
        }
    }

    // ---------------- weight prep (overlaps the loads above) ----------------
    float part = 0.0f;
    #pragma unroll
    for (int rep = 0; rep < 2; rep++) {
        const int i = t + rep * 512;              // 0..1023
        const int o = i >> 5, cc = i & 31;
        const float w = softplusf(__ldg(&channel_weight[i]));  // i = o*32 + cc
        const unsigned wu = __float_as_uint(w);
        scw2[cc * 32 + o] = ((unsigned long long)wu << 32) | wu;
        part += w;
    }
    #pragma unroll
    for (int off = 16; off > 0; off >>= 1)
        part += __shfl_xor_sync(0xffffffffu, part, off);
    if ((t & 31) == 0) swsums[t >> 5] = part;
    if (t < 32 * KK) s_sw[t] = softplusf(__ldg(&spatial_weight[t]));
    if (t < 32) {
        const float wp = softplusf(__ldg(&w_prop[t]));
        float S = 0.0f;
        #pragma unroll
        for (int k = 0; k < KK; k++)
            S += softplusf(__ldg(&spatial_weight[t * KK + k]));
        #pragma unroll
        for (int off = 16; off > 0; off >>= 1)
            S += __shfl_xor_sync(0xffffffffu, S, off);
        s_wp[t]    = wp;
        s_scale[t] = 1.0f / ((wp + 1.0f) * (S + EPS));
        sbias[t]   = __ldg(&bias[t]);
    }
    if (t >= 448 && t < 448 + 18) {
        const int i = t - 448;
        sUVo[i / 9][i % 9][0] = make_float2(0.0f, 0.0f);
    }
    __syncthreads();
    if (t == 0) {
        float s2 = 0.0f;
        #pragma unroll
        for (int w = 0; w < 16; w++) s2 += swsums[w];
        s_invS2_4 = 0.25f / (s2 + EPS);
    }

    // store channel 0 into buffer 0
    {
        const float wp0 = s_wp[0];
        stage_store(sUVe[0], sUVo[0], r_m, g4_m, wp0, L_s, L_cd, L_gx, L_cg);
        if (extra)
            stage_store(sUVe[0], sUVo[0], 8, g4_m, wp0, E_s, E_cd, E_gx, E_cg);
    }
    __syncthreads();

    // ---------------- main loop over channels ----------------
    unsigned long long acc[32];
    #pragma unroll
    for (int o = 0; o < 32; o++) acc[o] = 0ull;

    for (int c = 0; c < 32; ++c) {
        const int p  = c & 1;
        const int cn = c + 1;

        // prefetch channel c+1 (gmem latency covered by reduce below)
        float  spn[9];
        float4 N_s = {0,0,0,0}, N_cd = {0,0,0,0}, N_gx = {0,0,0,0}, N_cg = {0,0,0,0};
        float4 X_s = {0,0,0,0}, X_cd = {0,0,0,0}, X_gx = {0,0,0,0}, X_cg = {0,0,0,0};
        if (cn < 32) {
            const unsigned spb = (unsigned)(b * 32 + cn) * (KK * 16384u)
                               + (unsigned)ho * 128u + wo;
            #pragma unroll
            for (int k = 0; k < 9; k++)
                spn[k] = __ldcs(&sprod[spb + (unsigned)k * 16384u]);
            const unsigned plane = (unsigned)(b * 32 + cn) * 65536u;
            const int ir = ir0 + r_m;
            if ((unsigned)ir < 256u) {
                const unsigned base = plane + (unsigned)ir * 256u + g4_m * 4u;
                N_s  = *(const float4*)(s_in + base);
                N_cd = *(const float4*)(cd   + base);
                N_gx = *(const float4*)(gx   + base);
                N_cg = *(const float4*)(cgx  + base);
            }
            const int ir2 = ir0 + 8;
            if (extra && (unsigned)ir2 < 256u) {
                const unsigned base = plane + (unsigned)ir2 * 256u + g4_m * 4u;
                X_s  = *(const float4*)(s_in + base);
                X_cd = *(const float4*)(cd   + base);
                X_gx = *(const float4*)(gx   + base);
                X_cg = *(const float4*)(cgx  + base);
            }
        }

        // reduce channel c from buf[p]
        float nom = 0.0f, den = 0.0f;
        #pragma unroll
        for (int i = 0; i < 3; i++) {
            const int r = 2 * hloc + i;
            const float w0 = s_sw[c * KK + i * 3 + 0] * sp_cur[i * 3 + 0]; // x=2wo-1
            const float w1 = s_sw[c * KK + i * 3 + 1] * sp_cur[i * 3 + 1]; // x=2wo
            const float w2 = s_sw[c * KK + i * 3 + 2] * sp_cur[i * 3 + 2]; // x=2wo+1
            const float2 A  = sUVo[p][r][wo];
            const float2 Bv = sUVe[p][r][wo];
            const float2 D  = sUVo[p][r][wo + 1];
            nom += w0 * A.x + w1 * Bv.x + w2 * D.x;
            den += w0 * A.y + w1 * Bv.y + w2 * D.y;
        }
        const float scale = s_scale[c];
        const float P = nom * scale, Q = den * scale;
        const unsigned long long pq =
            ((unsigned long long)__float_as_uint(Q) << 32) | __float_as_uint(P);
        #pragma unroll
        for (int o = 0; o < 32; o++)
            FMA2(acc[o], pq, scw2[c * 32 + o]);

        // store channel c+1 into buf[1-p]
        if (cn < 32) {
            const float wpn = s_wp[cn];
            stage_store(sUVe[1 - p], sUVo[1 - p], r_m, g4_m, wpn,
                        N_s, N_cd, N_gx, N_cg);
            if (extra)
                stage_store(sUVe[1 - p], sUVo[1 - p], 8, g4_m, wpn,
                            X_s, X_cd, X_gx, X_cg);
        }
        __syncthreads();
        #pragma unroll
        for (int k = 0; k < 9; k++) sp_cur[k] = spn[k];
    }

    // ---------------- epilogue: divides + coalesced stores ----------------
    const float invS2_4 = s_invS2_4;
    const unsigned base0 = (unsigned)(b * 32) * 16384u + (unsigned)ho * 128u + wo;
    #pragma unroll
    for (int o = 0; o < 32; o++) {
        const float n = __uint_as_float((unsigned)acc[o]);
        const float d = __uint_as_float((unsigned)(acc[o] >> 32));
        out[base0 + o * 16384u] =
            (__fdividef(n, d + EPS) + sbias[o]) * 2.0f;
        out[2097152u + base0 + o * 16384u] = d * invS2_4;
    }
}

extern "C" void kernel_launch(void* const* d_in, const int* in_sizes, int n_in,
                              void* d_out, int out_size) {
    // metadata order: d, cd, s, cs, gx, cgx, s_prod_roll,
    //                 w_prop, spatial_weight, channel_weight, bias
    // (d and cs are provably unused — see stage1 simplification)
    const float* cd_p    = (const float*)d_in[1];
    const float* s_p     = (const float*)d_in[2];
    const float* gx_p    = (const float*)d_in[4];
    const float* cgx_p   = (const float*)d_in[5];
    const float* sprod_p = (const float*)d_in[6];
    const float* wprop_p = (const float*)d_in[7];
    const float* sw_p    = (const float*)d_in[8];
    const float* cw_p    = (const float*)d_in[9];
    const float* bias_p  = (const float*)d_in[10];

    fused_kernel<<<128, 512>>>(s_p, cd_p, gx_p, cgx_p, sprod_p,
                               wprop_p, sw_p, cw_p, bias_p, (float*)d_out);
}

// round 6
// speedup vs baseline: 1.3159x; 1.3159x over previous
#include <cuda_runtime.h>
#include <math.h>

#define EPS 1e-20f
#define Bn 4
#define Cn 32
#define On 32
#define Hn 256
#define Wn 256
#define HOn 128
#define WOn 128
#define HWO (HOn*WOn)      /* 16384 */
#define KK 9

// -------- device scratch (no allocations allowed) --------
__device__ float2 g_PQ[Bn*Cn*HWO];            // (cgx_sp*gx_sp, cgx_sp) interleaved
__device__ unsigned long long g_cw2[Cn*On];   // [c][o] softplus(cw) packed {w,w}
__device__ float g_invS2_4;                   // 0.25/(sum cw + eps)

__device__ __forceinline__ float softplusf(float x) {
    return fmaxf(x, 0.0f) + log1pf(expf(-fabsf(x)));
}

// packed f32x2 FMA (sm_103a FFMA2 — only reachable via PTX)
#define FMA2(acc, a, b) \
    asm("fma.rn.f32x2 %0, %1, %2, %3;" : "=l"(acc) : "l"(a), "l"(b), "l"(acc))

// -------- kernel 1: stage1 + spatial (per (b,c), 4 output rows per block) --------
// Stage1 exact simplification (reference's pad_r/pad_l are edge-zero masks):
//   cgx_from_ds = s^3 * cd^2 for 0<x<W-1, else 0;  gx_from_ds term contributes 0.
//   U = wp*cgx*gx ;  V = wp*cgx + cgx_from_ds
// Spatial: nom = sum_k sw_k*sprod_k*U_k/(wp+1);  den = sum_k sw_k*sprod_k*V_k/(wp+1)
//   P = nom/(S+eps) ;  Q = den/(S+eps)
__global__ __launch_bounds__(256) void spatial_kernel(
    const float* __restrict__ s_in, const float* __restrict__ cd,
    const float* __restrict__ gx,   const float* __restrict__ cgx,
    const float* __restrict__ sprod,
    const float* __restrict__ w_prop, const float* __restrict__ spatial_weight,
    const float* __restrict__ channel_weight)
{
    // parity-split tile, U,V packed: taps (2wo-1, 2wo, 2wo+1) -> odd[wo], even[wo], odd[wo+1]
    __shared__ float2 sUVe[9][128];
    __shared__ float2 sUVo[9][132];   // [0] = zero pad (x = -1)
    __shared__ float  s_sw[KK];
    __shared__ float  s_S;
    __shared__ float  s_cwsum[8];

    const int bc  = blockIdx.x;          // b*Cn + c
    const int c   = bc & (Cn - 1);
    const int ho0 = blockIdx.y * 4;
    const int ir0 = 2 * ho0 - 1;
    const int t   = threadIdx.x;

    const float wp = softplusf(__ldg(&w_prop[c]));

    // warp 0: sum of all 288 softplus(spatial_weight) via shuffle
    if (t < 32) {
        float acc = 0.0f;
        #pragma unroll
        for (int k = 0; k < KK; k++)
            acc += softplusf(__ldg(&spatial_weight[t * KK + k]));
        #pragma unroll
        for (int off = 16; off > 0; off >>= 1)
            acc += __shfl_xor_sync(0xffffffffu, acc, off);
        if (t == 0) s_S = acc;
    }
    if (t >= 32 && t < 32 + KK)
        s_sw[t - 32] = softplusf(__ldg(&spatial_weight[c * KK + (t - 32)]));
    if (t >= 64 && t < 64 + 9)
        sUVo[t - 64][0] = make_float2(0.0f, 0.0f);

    // block (0,0) additionally pre-packs channel weights for the channel kernel
    const bool cwblk = (blockIdx.x == 0) && (blockIdx.y == 0);
    if (cwblk) {
        float partial = 0.0f;
        #pragma unroll
        for (int i = t; i < Cn * On; i += 256) {
            const int o = i >> 5, cc = i & 31;
            const float w = softplusf(__ldg(&channel_weight[i]));  // i = o*Cn + cc
            const unsigned wu = __float_as_uint(w);
            g_cw2[cc * On + o] = ((unsigned long long)wu << 32) | wu;
            partial += w;
        }
        #pragma unroll
        for (int off = 16; off > 0; off >>= 1)
            partial += __shfl_xor_sync(0xffffffffu, partial, off);
        if ((t & 31) == 0) s_cwsum[t >> 5] = partial;
    }

    const size_t plane = (size_t)bc * (Hn * Wn);

    // ---- stage U,V for 9 input rows x 256 cols (float4-coalesced, streaming) ----
    for (int idx = t; idx < 9 * 64; idx += 256) {
        const int r  = idx >> 6;
        const int g4 = idx & 63;
        const int ir = ir0 + r;
        float u[4], v[4];
        if (ir >= 0 && ir < Hn) {
            const size_t base = plane + (size_t)ir * Wn + g4 * 4;
            const float4 sx  = __ldcs((const float4*)(s_in + base));
            const float4 cdx = __ldcs((const float4*)(cd   + base));
            const float4 gxx = __ldcs((const float4*)(gx   + base));
            const float4 cgv = __ldcs((const float4*)(cgx  + base));
            const float se[4]  = {sx.x,  sx.y,  sx.z,  sx.w};
            const float cde[4] = {cdx.x, cdx.y, cdx.z, cdx.w};
            const float ge[4]  = {gxx.x, gxx.y, gxx.z, gxx.w};
            const float cge[4] = {cgv.x, cgv.y, cgv.z, cgv.w};
            #pragma unroll
            for (int e = 0; e < 4; e++) {
                const int x = g4 * 4 + e;
                const float cgds = (x == 0 || x == Wn - 1)
                                 ? 0.0f
                                 : se[e] * se[e] * se[e] * cde[e] * cde[e];
                u[e] = wp * cge[e] * ge[e];
                v[e] = wp * cge[e] + cgds;
            }
        } else {
            #pragma unroll
            for (int e = 0; e < 4; e++) { u[e] = 0.0f; v[e] = 0.0f; }
        }
        // parity-split store: even x -> [x/2], odd x -> [x/2 + 1]
        sUVe[r][2 * g4]     = make_float2(u[0], v[0]);
        sUVo[r][2 * g4 + 1] = make_float2(u[1], v[1]);
        sUVe[r][2 * g4 + 1] = make_float2(u[2], v[2]);
        sUVo[r][2 * g4 + 2] = make_float2(u[3], v[3]);
    }
    __syncthreads();

    if (cwblk && t == 0) {
        g_invS2_4 = 0.25f / (s_cwsum[0] + s_cwsum[1] + s_cwsum[2] + s_cwsum[3]
                           + s_cwsum[4] + s_cwsum[5] + s_cwsum[6] + s_cwsum[7] + EPS);
    }

    const float scale = (1.0f / (wp + 1.0f)) * (1.0f / (s_S + EPS));

    // ---- spatial 3x3 stride-2 reduce (2 output pixels per thread) ----
    const int wo = t & 127;
    const int hb = t >> 7;            // 0 or 1
    #pragma unroll
    for (int it = 0; it < 2; ++it) {
        const int hloc = hb + it * 2;
        const int ho   = ho0 + hloc;
        float nom = 0.0f, den = 0.0f;
        const size_t spbase = (size_t)bc * KK * HWO + (size_t)ho * WOn + wo;
        #pragma unroll
        for (int i = 0; i < 3; i++) {
            const int r = 2 * hloc + i;
            const float sp0 = __ldcs(&sprod[spbase + (size_t)(i * 3 + 0) * HWO]);
            const float sp1 = __ldcs(&sprod[spbase + (size_t)(i * 3 + 1) * HWO]);
            const float sp2 = __ldcs(&sprod[spbase + (size_t)(i * 3 + 2) * HWO]);
            const float w0 = s_sw[i * 3 + 0] * sp0;   // x = 2wo-1 (odd)
            const float w1 = s_sw[i * 3 + 1] * sp1;   // x = 2wo   (even)
            const float w2 = s_sw[i * 3 + 2] * sp2;   // x = 2wo+1 (odd)
            const float2 a = sUVo[r][wo];
            const float2 b = sUVe[r][wo];
            const float2 d = sUVo[r][wo + 1];
            nom += w0 * a.x + w1 * b.x + w2 * d.x;
            den += w0 * a.y + w1 * b.y + w2 * d.y;
        }
        const size_t oidx = (size_t)bc * HWO + (size_t)ho * WOn + wo;
        g_PQ[oidx] = make_float2(nom * scale, den * scale);
    }
}

// -------- kernel 2: 1x1 channel mix; 4 threads/pixel (8 outputs each) --------
__global__ __launch_bounds__(256) void channel_kernel(
    const float* __restrict__ bias, float* __restrict__ out)
{
    __shared__ unsigned long long scw[Cn * 8];   // [cc][oo] for this block's 8 outputs
    __shared__ float sbias[8];
    const int t   = threadIdx.x;
    const int og0 = (blockIdx.x & 3) * 8;        // output quad: low bits -> L2 locality

    #pragma unroll
    for (int i = t; i < Cn * 8; i += 256) {
        const int cc = i >> 3, oo = i & 7;
        scw[i] = g_cw2[cc * On + og0 + oo];
    }
    if (t < 8) sbias[t] = __ldg(&bias[og0 + t]);
    __syncthreads();
    const float invS2_4 = g_invS2_4;

    const int px = (blockIdx.x >> 2) * 256 + t;
    const int b  = px >> 14;             // / HWO
    const int hw = px & (HWO - 1);

    const unsigned long long* PQ =
        (const unsigned long long*)g_PQ + (size_t)b * Cn * HWO + hw;

    unsigned long long acc[8];
    #pragma unroll
    for (int oo = 0; oo < 8; oo++) acc[oo] = 0ull;

    #pragma unroll
    for (int ccg = 0; ccg < Cn; ccg += 8) {
        unsigned long long pq[8];
        #pragma unroll
        for (int j = 0; j < 8; j++) pq[j] = PQ[(size_t)(ccg + j) * HWO];
        #pragma unroll
        for (int j = 0; j < 8; j++) {
            const unsigned long long p = pq[j];
            #pragma unroll
            for (int oo = 0; oo < 8; oo++)
                FMA2(acc[oo], p, scw[(ccg + j) * 8 + oo]);
        }
    }

    const size_t obase = (size_t)b * On * HWO + (size_t)og0 * HWO + hw;
    const size_t half  = (size_t)Bn * On * HWO;
    #pragma unroll
    for (int oo = 0; oo < 8; oo++) {
        const float n = __uint_as_float((unsigned)acc[oo]);
        const float d = __uint_as_float((unsigned)(acc[oo] >> 32));
        out[obase + (size_t)oo * HWO]        =
            (__fdividef(n, d + EPS) + sbias[oo]) * 2.0f;
        out[half + obase + (size_t)oo * HWO] = d * invS2_4;
    }
}

extern "C" void kernel_launch(void* const* d_in, const int* in_sizes, int n_in,
                              void* d_out, int out_size) {
    // metadata order: d, cd, s, cs, gx, cgx, s_prod_roll,
    //                 w_prop, spatial_weight, channel_weight, bias
    // (d and cs are provably unused — see stage1 simplification)
    const float* cd_p    = (const float*)d_in[1];
    const float* s_p     = (const float*)d_in[2];
    const float* gx_p    = (const float*)d_in[4];
    const float* cgx_p   = (const float*)d_in[5];
    const float* sprod_p = (const float*)d_in[6];
    const float* wprop_p = (const float*)d_in[7];
    const float* sw_p    = (const float*)d_in[8];
    const float* cw_p    = (const float*)d_in[9];
    const float* bias_p  = (const float*)d_in[10];

    dim3 gA(Bn * Cn, 32);            // 4096 blocks
    spatial_kernel<<<gA, 256>>>(s_p, cd_p, gx_p, cgx_p, sprod_p,
                                wprop_p, sw_p, cw_p);

    channel_kernel<<<1024, 256>>>(bias_p, (float*)d_out);
}

// round 7
// speedup vs baseline: 1.3279x; 1.0091x over previous
#include <cuda_runtime.h>
#include <math.h>

#define EPS 1e-20f
#define Bn 4
#define Cn 32
#define On 32
#define Hn 256
#define Wn 256
#define HOn 128
#define WOn 128
#define HWO (HOn*WOn)      /* 16384 */
#define KK 9

// -------- device scratch (no allocations allowed) --------
__device__ float2 g_PQ[Bn*Cn*HWO];            // (cgx_sp*gx_sp, cgx_sp) interleaved
__device__ unsigned long long g_cw2[Cn*On];   // [c][o] softplus(cw) packed {w,w}
__device__ float g_invS2_4;                   // 0.25/(sum cw + eps)

__device__ __forceinline__ float softplusf(float x) {
    return fmaxf(x, 0.0f) + log1pf(expf(-fabsf(x)));
}

// packed f32x2 FMA (sm_103a FFMA2 — only reachable via PTX)
#define FMA2(acc, a, b) \
    asm("fma.rn.f32x2 %0, %1, %2, %3;" : "=l"(acc) : "l"(a), "l"(b), "l"(acc))

// -------- kernel 1: stage1 + spatial (per (b,c), 4 output rows per block) --------
// Stage1 exact simplification (reference's pad_r/pad_l are edge-zero masks):
//   cgx_from_ds = s^3 * cd^2 for 0<x<W-1, else 0;  gx_from_ds term contributes 0.
//   U = wp*cgx*gx ;  V = wp*cgx + cgx_from_ds
// Spatial: nom = sum_k sw_k*sprod_k*U_k/(wp+1);  den = sum_k sw_k*sprod_k*V_k/(wp+1)
//   P = nom/(S+eps) ;  Q = den/(S+eps)
__global__ __launch_bounds__(256) void spatial_kernel(
    const float* __restrict__ s_in, const float* __restrict__ cd,
    const float* __restrict__ gx,   const float* __restrict__ cgx,
    const float* __restrict__ sprod,
    const float* __restrict__ w_prop, const float* __restrict__ spatial_weight,
    const float* __restrict__ channel_weight)
{
    // parity-split tile, U,V packed: taps (2wo-1, 2wo, 2wo+1) -> odd[wo], even[wo], odd[wo+1]
    __shared__ float2 sUVe[9][128];
    __shared__ float2 sUVo[9][132];   // [0] = zero pad (x = -1)
    __shared__ float  s_sw[KK];
    __shared__ float  s_S;
    __shared__ float  s_cwsum[8];

    const int bc  = blockIdx.x;          // b*Cn + c
    const int c   = bc & (Cn - 1);
    const int ho0 = blockIdx.y * 4;
    const int ir0 = 2 * ho0 - 1;
    const int t   = threadIdx.x;

    const float wp = softplusf(__ldg(&w_prop[c]));

    // warp 0: sum of all 288 softplus(spatial_weight) via shuffle
    if (t < 32) {
        float acc = 0.0f;
        #pragma unroll
        for (int k = 0; k < KK; k++)
            acc += softplusf(__ldg(&spatial_weight[t * KK + k]));
        #pragma unroll
        for (int off = 16; off > 0; off >>= 1)
            acc += __shfl_xor_sync(0xffffffffu, acc, off);
        if (t == 0) s_S = acc;
    }
    if (t >= 32 && t < 32 + KK)
        s_sw[t - 32] = softplusf(__ldg(&spatial_weight[c * KK + (t - 32)]));
    if (t >= 64 && t < 64 + 9)
        sUVo[t - 64][0] = make_float2(0.0f, 0.0f);

    // block (0,0) additionally pre-packs channel weights for the channel kernel
    const bool cwblk = (blockIdx.x == 0) && (blockIdx.y == 0);
    if (cwblk) {
        float partial = 0.0f;
        #pragma unroll
        for (int i = t; i < Cn * On; i += 256) {
            const int o = i >> 5, cc = i & 31;
            const float w = softplusf(__ldg(&channel_weight[i]));  // i = o*Cn + cc
            const unsigned wu = __float_as_uint(w);
            g_cw2[cc * On + o] = ((unsigned long long)wu << 32) | wu;
            partial += w;
        }
        #pragma unroll
        for (int off = 16; off > 0; off >>= 1)
            partial += __shfl_xor_sync(0xffffffffu, partial, off);
        if ((t & 31) == 0) s_cwsum[t >> 5] = partial;
    }

    const size_t plane = (size_t)bc * (Hn * Wn);

    // ---- stage U,V for 9 input rows x 256 cols (float4-coalesced, streaming) ----
    for (int idx = t; idx < 9 * 64; idx += 256) {
        const int r  = idx >> 6;
        const int g4 = idx & 63;
        const int ir = ir0 + r;
        float u[4], v[4];
        if (ir >= 0 && ir < Hn) {
            const size_t base = plane + (size_t)ir * Wn + g4 * 4;
            const float4 sx  = __ldcs((const float4*)(s_in + base));
            const float4 cdx = __ldcs((const float4*)(cd   + base));
            const float4 gxx = __ldcs((const float4*)(gx   + base));
            const float4 cgv = __ldcs((const float4*)(cgx  + base));
            const float se[4]  = {sx.x,  sx.y,  sx.z,  sx.w};
            const float cde[4] = {cdx.x, cdx.y, cdx.z, cdx.w};
            const float ge[4]  = {gxx.x, gxx.y, gxx.z, gxx.w};
            const float cge[4] = {cgv.x, cgv.y, cgv.z, cgv.w};
            #pragma unroll
            for (int e = 0; e < 4; e++) {
                const int x = g4 * 4 + e;
                const float cgds = (x == 0 || x == Wn - 1)
                                 ? 0.0f
                                 : se[e] * se[e] * se[e] * cde[e] * cde[e];
                u[e] = wp * cge[e] * ge[e];
                v[e] = wp * cge[e] + cgds;
            }
        } else {
            #pragma unroll
            for (int e = 0; e < 4; e++) { u[e] = 0.0f; v[e] = 0.0f; }
        }
        // parity-split store: even x -> [x/2], odd x -> [x/2 + 1]
        sUVe[r][2 * g4]     = make_float2(u[0], v[0]);
        sUVo[r][2 * g4 + 1] = make_float2(u[1], v[1]);
        sUVe[r][2 * g4 + 1] = make_float2(u[2], v[2]);
        sUVo[r][2 * g4 + 2] = make_float2(u[3], v[3]);
    }
    __syncthreads();

    if (cwblk && t == 0) {
        g_invS2_4 = 0.25f / (s_cwsum[0] + s_cwsum[1] + s_cwsum[2] + s_cwsum[3]
                           + s_cwsum[4] + s_cwsum[5] + s_cwsum[6] + s_cwsum[7] + EPS);
    }

    const float scale = (1.0f / (wp + 1.0f)) * (1.0f / (s_S + EPS));

    // ---- spatial 3x3 stride-2 reduce (2 output pixels per thread) ----
    const int wo = t & 127;
    const int hb = t >> 7;            // 0 or 1
    #pragma unroll
    for (int it = 0; it < 2; ++it) {
        const int hloc = hb + it * 2;
        const int ho   = ho0 + hloc;
        float nom = 0.0f, den = 0.0f;
        const size_t spbase = (size_t)bc * KK * HWO + (size_t)ho * WOn + wo;
        #pragma unroll
        for (int i = 0; i < 3; i++) {
            const int r = 2 * hloc + i;
            const float sp0 = __ldcs(&sprod[spbase + (size_t)(i * 3 + 0) * HWO]);
            const float sp1 = __ldcs(&sprod[spbase + (size_t)(i * 3 + 1) * HWO]);
            const float sp2 = __ldcs(&sprod[spbase + (size_t)(i * 3 + 2) * HWO]);
            const float w0 = s_sw[i * 3 + 0] * sp0;   // x = 2wo-1 (odd)
            const float w1 = s_sw[i * 3 + 1] * sp1;   // x = 2wo   (even)
            const float w2 = s_sw[i * 3 + 2] * sp2;   // x = 2wo+1 (odd)
            const float2 a = sUVo[r][wo];
            const float2 b = sUVe[r][wo];
            const float2 d = sUVo[r][wo + 1];
            nom += w0 * a.x + w1 * b.x + w2 * d.x;
            den += w0 * a.y + w1 * b.y + w2 * d.y;
        }
        const size_t oidx = (size_t)bc * HWO + (size_t)ho * WOn + wo;
        g_PQ[oidx] = make_float2(nom * scale, den * scale);
    }
}

// -------- kernel 2: 1x1 channel mix; 2 pixels x 8 outputs per thread --------
// LDG.128 fetches both pixels' (P,Q); each weight LDS feeds 2 FMA2.
__global__ __launch_bounds__(256) void channel_kernel(
    const float* __restrict__ bias, float* __restrict__ out)
{
    __shared__ unsigned long long scw[Cn * 8];   // [cc][oo] for this block's 8 outputs
    __shared__ float sbias[8];
    const int t   = threadIdx.x;
    const int og0 = (blockIdx.x & 3) * 8;        // output quad: low bits -> L2 locality

    #pragma unroll
    for (int i = t; i < Cn * 8; i += 256) {
        const int cc = i >> 3, oo = i & 7;
        scw[i] = g_cw2[cc * On + og0 + oo];
    }
    if (t < 8) sbias[t] = __ldg(&bias[og0 + t]);
    __syncthreads();
    const float invS2_4 = g_invS2_4;

    const int px = ((blockIdx.x >> 2) * 256 + t) * 2;   // first of 2 adjacent pixels
    const int b  = px >> 14;             // / HWO
    const int hw = px & (HWO - 1);       // even

    const uint4* PQ = (const uint4*)g_PQ + ((size_t)b * Cn * HWO + hw) / 2;

    unsigned long long a0[8], a1[8];
    #pragma unroll
    for (int oo = 0; oo < 8; oo++) { a0[oo] = 0ull; a1[oo] = 0ull; }

    #pragma unroll
    for (int ccg = 0; ccg < Cn; ccg += 8) {
        uint4 pq[8];
        #pragma unroll
        for (int j = 0; j < 8; j++) pq[j] = PQ[(size_t)(ccg + j) * (HWO / 2)];
        #pragma unroll
        for (int j = 0; j < 8; j++) {
            const unsigned long long p0 =
                ((unsigned long long)pq[j].y << 32) | pq[j].x;
            const unsigned long long p1 =
                ((unsigned long long)pq[j].w << 32) | pq[j].z;
            #pragma unroll
            for (int oo = 0; oo < 8; oo++) {
                const unsigned long long w = scw[(ccg + j) * 8 + oo];
                FMA2(a0[oo], p0, w);
                FMA2(a1[oo], p1, w);
            }
        }
    }

    const size_t obase = (size_t)b * On * HWO + (size_t)og0 * HWO + hw;
    const size_t half  = (size_t)Bn * On * HWO;
    #pragma unroll
    for (int oo = 0; oo < 8; oo++) {
        const float n0 = __uint_as_float((unsigned)a0[oo]);
        const float d0 = __uint_as_float((unsigned)(a0[oo] >> 32));
        const float n1 = __uint_as_float((unsigned)a1[oo]);
        const float d1 = __uint_as_float((unsigned)(a1[oo] >> 32));
        const float g0 = (__fdividef(n0, d0 + EPS) + sbias[oo]) * 2.0f;
        const float g1 = (__fdividef(n1, d1 + EPS) + sbias[oo]) * 2.0f;
        *(float2*)&out[obase + (size_t)oo * HWO]        = make_float2(g0, g1);
        *(float2*)&out[half + obase + (size_t)oo * HWO] =
            make_float2(d0 * invS2_4, d1 * invS2_4);
    }
}

extern "C" void kernel_launch(void* const* d_in, const int* in_sizes, int n_in,
                              void* d_out, int out_size) {
    // metadata order: d, cd, s, cs, gx, cgx, s_prod_roll,
    //                 w_prop, spatial_weight, channel_weight, bias
    // (d and cs are provably unused — see stage1 simplification)
    const float* cd_p    = (const float*)d_in[1];
    const float* s_p     = (const float*)d_in[2];
    const float* gx_p    = (const float*)d_in[4];
    const float* cgx_p   = (const float*)d_in[5];
    const float* sprod_p = (const float*)d_in[6];
    const float* wprop_p = (const float*)d_in[7];
    const float* sw_p    = (const float*)d_in[8];
    const float* cw_p    = (const float*)d_in[9];
    const float* bias_p  = (const float*)d_in[10];

    dim3 gA(Bn * Cn, 32);            // 4096 blocks
    spatial_kernel<<<gA, 256>>>(s_p, cd_p, gx_p, cgx_p, sprod_p,
                                wprop_p, sw_p, cw_p);

    // 65536 pixels / 2 per thread = 32768 threads per og-quad; x4 quads = 512 blocks
    channel_kernel<<<512, 256>>>(bias_p, (float*)d_out);
}